// round 1
// baseline (speedup 1.0000x reference)
#include <cuda_runtime.h>

#define NN 50000
#define NE 800000
#define FF 128
#define NG 128

// ---- device scratch (allocation-free rule: __device__ globals) ----
__device__ __align__(16) float g_h[NN * FF];   // GEMM output
__device__ __align__(16) float g_a[NN * FF];   // aggregated output
__device__ int   g_cnt[NN];
__device__ float g_dinv[NN];
__device__ int   g_rowptr[NN + 1];
__device__ int   g_cursor[NN];
__device__ int   g_col[NE];
__device__ __align__(16) float g_wgt[NE];
__device__ int   g_gstart[NG + 1];

// ---------------- init ----------------
__global__ void init_kernel() {
    int i = blockIdx.x * blockDim.x + threadIdx.x;
    if (i < NN) g_cnt[i] = 0;
    if (i <= NG) g_gstart[i] = NN;
}

// ---------------- degree histogram over dst ----------------
__global__ void count_kernel(const int* __restrict__ ei) {
    int e = blockIdx.x * blockDim.x + threadIdx.x;
    if (e < NE) atomicAdd(&g_cnt[ei[NE + e]], 1);
}

__global__ void dinv_kernel() {
    int i = blockIdx.x * blockDim.x + threadIdx.x;
    if (i < NN) g_dinv[i] = rsqrtf((float)g_cnt[i] + 1.0f);
}

// ---------------- single-block exclusive scan (50001 entries) ----------------
__global__ void scan_kernel() {
    __shared__ int warpsum[32];
    __shared__ int carry_s;
    int tid = threadIdx.x, lane = tid & 31, wid = tid >> 5;
    if (tid == 0) carry_s = 0;
    __syncthreads();
    for (int base = 0; base < NN; base += 1024) {
        int i = base + tid;
        int v = (i < NN) ? g_cnt[i] : 0;
        int s = v;
        #pragma unroll
        for (int off = 1; off < 32; off <<= 1) {
            int t = __shfl_up_sync(0xffffffffu, s, off);
            if (lane >= off) s += t;
        }
        if (lane == 31) warpsum[wid] = s;
        __syncthreads();
        if (wid == 0) {
            int ws = warpsum[lane];
            #pragma unroll
            for (int off = 1; off < 32; off <<= 1) {
                int t = __shfl_up_sync(0xffffffffu, ws, off);
                if (lane >= off) ws += t;
            }
            warpsum[lane] = ws;
        }
        __syncthreads();
        int wbase = (wid > 0) ? warpsum[wid - 1] : 0;
        if (i < NN) g_rowptr[i] = carry_s + wbase + (s - v);
        __syncthreads();
        if (tid == 0) carry_s += warpsum[31];
        __syncthreads();
    }
    if (threadIdx.x == 0) g_rowptr[NN] = carry_s;
}

// ---------------- cursor copy + per-graph start (batch sorted) ----------------
__global__ void prep_kernel(const int* __restrict__ batch) {
    int i = blockIdx.x * blockDim.x + threadIdx.x;
    if (i < NN) {
        g_cursor[i] = g_rowptr[i];
        atomicMin(&g_gstart[batch[i]], i);
    }
}

// ---------------- CSR fill ----------------
__global__ void fill_kernel(const int* __restrict__ ei) {
    int e = blockIdx.x * blockDim.x + threadIdx.x;
    if (e < NE) {
        int src = ei[e], dst = ei[NE + e];
        int pos = atomicAdd(&g_cursor[dst], 1);
        g_col[pos] = src;
        g_wgt[pos] = g_dinv[src] * g_dinv[dst];
    }
}

// ---------------- fixup empty graphs (serial, trivial) ----------------
__global__ void gfix_kernel() {
    if (threadIdx.x == 0 && blockIdx.x == 0) {
        for (int g = NG - 1; g >= 0; g--)
            if (g_gstart[g] == NN) g_gstart[g] = g_gstart[g + 1];
    }
}

// ---------------- fp32 GEMM: C[NN,128] = A[NN,128] @ W[128,128] ----------------
// 128x128 tile per block, 256 threads, 8x8 microtile. K=128 fully in smem.
__global__ __launch_bounds__(256) void gemm_kernel(const float* __restrict__ Ain,
                                                   const float* __restrict__ W,
                                                   int use_ga) {
    extern __shared__ float sm[];
    float* As = sm;               // [128][128] row-major (r, k)
    float* Ws = sm + 128 * 128;   // [128][128] row-major (k, c)
    const float* A = use_ga ? g_a : Ain;
    int tid = threadIdx.x;
    int row0 = blockIdx.x * 128;

    const float4* Wv = (const float4*)W;
    float4* Wsv = (float4*)Ws;
    #pragma unroll
    for (int i = 0; i < 16; i++) Wsv[tid + 256 * i] = Wv[tid + 256 * i];

    const float4* Av = (const float4*)A;
    float4* Asv = (float4*)As;
    #pragma unroll
    for (int i = 0; i < 16; i++) {
        int li = tid + 256 * i;         // float4 slot: row = li>>5, kquad = li&31
        int r = li >> 5;
        float4 v = make_float4(0.f, 0.f, 0.f, 0.f);
        int grow = row0 + r;
        if (grow < NN) v = Av[grow * 32 + (li & 31)];
        Asv[li] = v;
    }
    __syncthreads();

    int tx = tid & 15, ty = tid >> 4;   // cols 8*tx.., rows 8*ty..
    const float* Arow = As + ty * 8 * 128;
    const float* Wcol = Ws + tx * 8;
    float acc[8][8] = {};
    #pragma unroll 2
    for (int k = 0; k < 128; k++) {
        float a[8], b[8];
        #pragma unroll
        for (int i = 0; i < 8; i++) a[i] = Arow[i * 128 + k];
        float4 b0 = *(const float4*)(Wcol + k * 128);
        float4 b1 = *(const float4*)(Wcol + k * 128 + 4);
        b[0] = b0.x; b[1] = b0.y; b[2] = b0.z; b[3] = b0.w;
        b[4] = b1.x; b[5] = b1.y; b[6] = b1.z; b[7] = b1.w;
        #pragma unroll
        for (int i = 0; i < 8; i++)
            #pragma unroll
            for (int j = 0; j < 8; j++) acc[i][j] += a[i] * b[j];
    }
    #pragma unroll
    for (int i = 0; i < 8; i++) {
        int grow = row0 + ty * 8 + i;
        if (grow < NN) {
            float4* Cp = (float4*)(g_h + grow * 128 + tx * 8);
            Cp[0] = make_float4(acc[i][0], acc[i][1], acc[i][2], acc[i][3]);
            Cp[1] = make_float4(acc[i][4], acc[i][5], acc[i][6], acc[i][7]);
        }
    }
}

// ---------------- aggregation: warp per node, float4 per lane ----------------
// out[i] = bias + dinv[i]^2 * h[i] + sum_e nrm[e] * h[col[e]]; optional ReLU
__global__ void agg_kernel(const float* __restrict__ bias, int relu) {
    int gw = (blockIdx.x * blockDim.x + threadIdx.x) >> 5;
    int lane = threadIdx.x & 31;
    if (gw >= NN) return;
    const float4* h4 = (const float4*)g_h;
    float4 acc = ((const float4*)bias)[lane];
    float di = g_dinv[gw];
    float s = di * di;
    float4 hv = h4[gw * 32 + lane];
    acc.x += s * hv.x; acc.y += s * hv.y; acc.z += s * hv.z; acc.w += s * hv.w;

    int e = g_rowptr[gw], ee = g_rowptr[gw + 1];
    for (; e + 4 <= ee; e += 4) {
        int c0 = g_col[e], c1 = g_col[e + 1], c2 = g_col[e + 2], c3 = g_col[e + 3];
        float w0 = g_wgt[e], w1 = g_wgt[e + 1], w2 = g_wgt[e + 2], w3 = g_wgt[e + 3];
        float4 v0 = h4[c0 * 32 + lane];
        float4 v1 = h4[c1 * 32 + lane];
        float4 v2 = h4[c2 * 32 + lane];
        float4 v3 = h4[c3 * 32 + lane];
        acc.x += w0 * v0.x; acc.y += w0 * v0.y; acc.z += w0 * v0.z; acc.w += w0 * v0.w;
        acc.x += w1 * v1.x; acc.y += w1 * v1.y; acc.z += w1 * v1.z; acc.w += w1 * v1.w;
        acc.x += w2 * v2.x; acc.y += w2 * v2.y; acc.z += w2 * v2.z; acc.w += w2 * v2.w;
        acc.x += w3 * v3.x; acc.y += w3 * v3.y; acc.z += w3 * v3.z; acc.w += w3 * v3.w;
    }
    for (; e < ee; e++) {
        int c = g_col[e];
        float w = g_wgt[e];
        float4 v = h4[c * 32 + lane];
        acc.x += w * v.x; acc.y += w * v.y; acc.z += w * v.z; acc.w += w * v.w;
    }
    if (relu) {
        acc.x = fmaxf(acc.x, 0.f); acc.y = fmaxf(acc.y, 0.f);
        acc.z = fmaxf(acc.z, 0.f); acc.w = fmaxf(acc.w, 0.f);
    }
    ((float4*)g_a)[gw * 32 + lane] = acc;
}

// ---------------- pool: block per graph (batch sorted -> contiguous ranges) ----------------
__global__ void pool_kernel(float* __restrict__ out) {
    int g = blockIdx.x;
    int c = threadIdx.x;  // 128 threads: one column each
    int sidx = g_gstart[g], eidx = g_gstart[g + 1];
    float acc = 0.f;
    int i = sidx;
    for (; i + 4 <= eidx; i += 4) {
        float t0 = g_a[i * 128 + c];
        float t1 = g_a[(i + 1) * 128 + c];
        float t2 = g_a[(i + 2) * 128 + c];
        float t3 = g_a[(i + 3) * 128 + c];
        acc += (t0 + t1) + (t2 + t3);
    }
    for (; i < eidx; i++) acc += g_a[i * 128 + c];
    out[g * 128 + c] = acc;
}

extern "C" void kernel_launch(void* const* d_in, const int* in_sizes, int n_in,
                              void* d_out, int out_size) {
    const float* x     = (const float*)d_in[0];
    const int*   ei    = (const int*)d_in[1];
    const int*   batch = (const int*)d_in[2];
    const float* W1    = (const float*)d_in[3];
    const float* b1    = (const float*)d_in[4];
    const float* W2    = (const float*)d_in[5];
    const float* b2    = (const float*)d_in[6];
    float* out = (float*)d_out;

    cudaFuncSetAttribute(gemm_kernel, cudaFuncAttributeMaxDynamicSharedMemorySize, 131072);

    // CSR + norm construction (per launch; deterministic up to fp-order)
    init_kernel<<<(NN + 255) / 256, 256>>>();
    count_kernel<<<(NE + 255) / 256, 256>>>(ei);
    dinv_kernel<<<(NN + 255) / 256, 256>>>();
    scan_kernel<<<1, 1024>>>();
    prep_kernel<<<(NN + 255) / 256, 256>>>(batch);
    fill_kernel<<<(NE + 255) / 256, 256>>>(ei);
    gfix_kernel<<<1, 32>>>();

    // Layer 1: h = x@W1 ; a = relu(agg(h) + self + b1)
    gemm_kernel<<<(NN + 127) / 128, 256, 131072>>>(x, W1, 0);
    agg_kernel<<<(NN * 32 + 255) / 256, 256>>>(b1, 1);

    // Layer 2: h = a@W2 ; a = agg(h) + self + b2
    gemm_kernel<<<(NN + 127) / 128, 256, 131072>>>(nullptr, W2, 1);
    agg_kernel<<<(NN * 32 + 255) / 256, 256>>>(b2, 0);

    // Global add pool
    pool_kernel<<<NG, 128>>>(out);
}

// round 2
// speedup vs baseline: 1.6586x; 1.6586x over previous
#include <cuda_runtime.h>
#include <cuda_bf16.h>

#define NN 50000
#define NE 800000
#define FF 128
#define NG 128
#define NSCANB ((NN + 255) / 256)   // 196

// ---- device scratch ----
__device__ __align__(16) float g_h[NN * FF];
__device__ __align__(16) float g_a[NN * FF];
__device__ int   g_cnt[NN];
__device__ float g_dinv[NN];
__device__ int   g_rowptr[NN + 1];
__device__ int   g_cursor[NN];
__device__ int   g_col[NE];
__device__ __align__(16) float g_wgt[NE];
__device__ int   g_gstart[NG + 1];
__device__ int   g_bsum[NSCANB];
__device__ int   g_boff[NSCANB];
__device__ __align__(16) uint4 g_packW[2][4096];   // [kc*16+nc][lane] -> {bhi0,bhi1,blo0,blo1}

// ---------------- init ----------------
__global__ void init_kernel() {
    int i = blockIdx.x * blockDim.x + threadIdx.x;
    if (i < NN) g_cnt[i] = 0;
    if (i <= NG) g_gstart[i] = NN;
}

__global__ void count_kernel(const int* __restrict__ ei) {
    int e = blockIdx.x * blockDim.x + threadIdx.x;
    if (e < NE) atomicAdd(&g_cnt[ei[NE + e]], 1);
}

// ---------------- hierarchical scan ----------------
// pass 1: block-local exclusive scan of g_cnt -> g_rowptr (partial), block totals -> g_bsum
//         also computes g_dinv.
__global__ __launch_bounds__(256) void blockscan_kernel() {
    __shared__ int wsum[8];
    int i = blockIdx.x * 256 + threadIdx.x;
    int lane = threadIdx.x & 31, wid = threadIdx.x >> 5;
    int v = (i < NN) ? g_cnt[i] : 0;
    if (i < NN) g_dinv[i] = rsqrtf((float)v + 1.0f);
    int s = v;
    #pragma unroll
    for (int off = 1; off < 32; off <<= 1) {
        int t = __shfl_up_sync(0xffffffffu, s, off);
        if (lane >= off) s += t;
    }
    if (lane == 31) wsum[wid] = s;
    __syncthreads();
    if (wid == 0 && lane < 8) {
        int ws = wsum[lane];
        #pragma unroll
        for (int off = 1; off < 8; off <<= 1) {
            int t = __shfl_up_sync(0xffu, ws, off);
            if (lane >= off) ws += t;
        }
        wsum[lane] = ws;
    }
    __syncthreads();
    int wbase = (wid > 0) ? wsum[wid - 1] : 0;
    if (i < NN) g_rowptr[i] = wbase + (s - v);
    if (threadIdx.x == 255) g_bsum[blockIdx.x] = wsum[7];
}

// pass 2: exclusive scan of NSCANB block sums (single block, 256 threads)
__global__ __launch_bounds__(256) void scansums_kernel() {
    __shared__ int wsum[8];
    int i = threadIdx.x;
    int lane = i & 31, wid = i >> 5;
    int v = (i < NSCANB) ? g_bsum[i] : 0;
    int s = v;
    #pragma unroll
    for (int off = 1; off < 32; off <<= 1) {
        int t = __shfl_up_sync(0xffffffffu, s, off);
        if (lane >= off) s += t;
    }
    if (lane == 31) wsum[wid] = s;
    __syncthreads();
    if (wid == 0 && lane < 8) {
        int ws = wsum[lane];
        #pragma unroll
        for (int off = 1; off < 8; off <<= 1) {
            int t = __shfl_up_sync(0xffu, ws, off);
            if (lane >= off) ws += t;
        }
        wsum[lane] = ws;
    }
    __syncthreads();
    int wbase = (wid > 0) ? wsum[wid - 1] : 0;
    if (i < NSCANB) g_boff[i] = wbase + (s - v);
    if (i == 0) g_rowptr[NN] = NE;   // total edge count is known
}

// pass 3: add block offsets; init cursor; per-graph starts
__global__ __launch_bounds__(256) void addoff_kernel(const int* __restrict__ batch) {
    int i = blockIdx.x * 256 + threadIdx.x;
    if (i < NN) {
        int r = g_rowptr[i] + g_boff[blockIdx.x];
        g_rowptr[i] = r;
        g_cursor[i] = r;
        atomicMin(&g_gstart[batch[i]], i);
    }
}

__global__ void fill_kernel(const int* __restrict__ ei) {
    int e = blockIdx.x * blockDim.x + threadIdx.x;
    if (e < NE) {
        int src = ei[e], dst = ei[NE + e];
        int pos = atomicAdd(&g_cursor[dst], 1);
        g_col[pos] = src;
        g_wgt[pos] = g_dinv[src] * g_dinv[dst];
    }
}

__global__ void gfix_kernel() {
    if (threadIdx.x == 0 && blockIdx.x == 0) {
        for (int g = NG - 1; g >= 0; g--)
            if (g_gstart[g] == NN) g_gstart[g] = g_gstart[g + 1];
    }
}

// ---------------- bf16 split helpers ----------------
__device__ __forceinline__ void bsplit2(float x, float y, unsigned& hi, unsigned& lo) {
    __nv_bfloat162 h = __floats2bfloat162_rn(x, y);
    float rx = x - __bfloat162float(h.x);
    float ry = y - __bfloat162float(h.y);
    __nv_bfloat162 l = __floats2bfloat162_rn(rx, ry);
    hi = *reinterpret_cast<unsigned*>(&h);
    lo = *reinterpret_cast<unsigned*>(&l);
}

// ---------------- W pack: mma fragment layout, hi/lo split ----------------
// packed[which][chunk*32+lane] = {whi_reg0, whi_reg1, wlo_reg0, wlo_reg1}
// chunk = kc*16+nc ; B frag: b0=B[kb+2tg][n], b1=B[kb+2tg+1][n], b2=B[kb+2tg+8][n], b3=B[kb+2tg+9][n]
__global__ __launch_bounds__(256) void pack_kernel(const float* __restrict__ W1,
                                                   const float* __restrict__ W2) {
    int idx = blockIdx.x * 256 + threadIdx.x;      // 0..8191
    int which = idx >> 12;
    int t = idx & 4095;
    const float* W = which ? W2 : W1;
    int lane = t & 31, chunk = t >> 5;
    int kc = chunk >> 4, nc = chunk & 15;
    int g = lane >> 2, tg = lane & 3;
    int n = nc * 8 + g, kb = kc * 16;
    float w0 = W[(kb + 2 * tg) * 128 + n];
    float w1 = W[(kb + 2 * tg + 1) * 128 + n];
    float w2 = W[(kb + 2 * tg + 8) * 128 + n];
    float w3 = W[(kb + 2 * tg + 9) * 128 + n];
    unsigned h0, l0, h1, l1;
    bsplit2(w0, w1, h0, l0);
    bsplit2(w2, w3, h1, l1);
    g_packW[which][t] = make_uint4(h0, h1, l0, l1);
}

// ---------------- tensor-core GEMM: C[NN,128] = A[NN,128] @ W ----------------
// bf16x2-split (hi*hi + hi*lo + lo*hi), mma.sync.m16n8k16.
// 256 thr = 8 warps; warp computes 16 rows x 128 cols. Block = 128 rows.
#define MMA_BF16(c0,c1,c2,c3,a0,a1,a2,a3,b0,b1)                                \
    asm volatile("mma.sync.aligned.m16n8k16.row.col.f32.bf16.bf16.f32 "        \
                 "{%0,%1,%2,%3}, {%4,%5,%6,%7}, {%8,%9}, {%0,%1,%2,%3};"       \
                 : "+f"(c0), "+f"(c1), "+f"(c2), "+f"(c3)                      \
                 : "r"(a0), "r"(a1), "r"(a2), "r"(a3), "r"(b0), "r"(b1))

__global__ __launch_bounds__(256) void gemm_mma_kernel(const float* __restrict__ Ain,
                                                       int use_ga, int wsel) {
    extern __shared__ uint4 sW[];   // 4096 uint4 = 64KB
    const float* __restrict__ A = use_ga ? g_a : Ain;
    int tid = threadIdx.x;
    const uint4* __restrict__ pW = g_packW[wsel];
    #pragma unroll
    for (int i = 0; i < 16; i++) sW[tid + 256 * i] = pW[tid + 256 * i];
    __syncthreads();

    int warp = tid >> 5, lane = tid & 31;
    int g = lane >> 2, tg = lane & 3;
    int row0 = blockIdx.x * 128 + warp * 16;
    int r0 = row0 + g, r1 = row0 + g + 8;
    int r0c = (r0 < NN) ? r0 : 0;
    int r1c = (r1 < NN) ? r1 : 0;

    float acc[16][4];
    #pragma unroll
    for (int nc = 0; nc < 16; nc++)
        #pragma unroll
        for (int j = 0; j < 4; j++) acc[nc][j] = 0.f;

    #pragma unroll
    for (int kc = 0; kc < 8; kc++) {
        const float* Ar0 = A + (size_t)r0c * 128 + kc * 16;
        const float* Ar1 = A + (size_t)r1c * 128 + kc * 16;
        float2 f00 = *(const float2*)(Ar0 + 2 * tg);
        float2 f01 = *(const float2*)(Ar0 + 2 * tg + 8);
        float2 f10 = *(const float2*)(Ar1 + 2 * tg);
        float2 f11 = *(const float2*)(Ar1 + 2 * tg + 8);
        unsigned ah0, al0, ah1, al1, ah2, al2, ah3, al3;
        bsplit2(f00.x, f00.y, ah0, al0);   // a-reg0: row g,   k lo
        bsplit2(f10.x, f10.y, ah1, al1);   // a-reg1: row g+8, k lo
        bsplit2(f01.x, f01.y, ah2, al2);   // a-reg2: row g,   k hi
        bsplit2(f11.x, f11.y, ah3, al3);   // a-reg3: row g+8, k hi

        const uint4* wrow = sW + kc * 16 * 32 + lane;
        #pragma unroll
        for (int nc = 0; nc < 16; nc++) {
            uint4 w = wrow[nc * 32];
            MMA_BF16(acc[nc][0], acc[nc][1], acc[nc][2], acc[nc][3],
                     ah0, ah1, ah2, ah3, w.x, w.y);            // hi*hi
            MMA_BF16(acc[nc][0], acc[nc][1], acc[nc][2], acc[nc][3],
                     ah0, ah1, ah2, ah3, w.z, w.w);            // hi*lo
            MMA_BF16(acc[nc][0], acc[nc][1], acc[nc][2], acc[nc][3],
                     al0, al1, al2, al3, w.x, w.y);            // lo*hi
        }
    }

    #pragma unroll
    for (int nc = 0; nc < 16; nc++) {
        int col = nc * 8 + 2 * tg;
        if (r0 < NN) *(float2*)(g_h + (size_t)r0 * 128 + col) = make_float2(acc[nc][0], acc[nc][1]);
        if (r1 < NN) *(float2*)(g_h + (size_t)r1 * 128 + col) = make_float2(acc[nc][2], acc[nc][3]);
    }
}

// ---------------- aggregation: warp per node ----------------
__global__ void agg_kernel(const float* __restrict__ bias, int relu) {
    int gw = (blockIdx.x * blockDim.x + threadIdx.x) >> 5;
    int lane = threadIdx.x & 31;
    if (gw >= NN) return;
    const float4* h4 = (const float4*)g_h;
    float4 acc = ((const float4*)bias)[lane];
    float di = g_dinv[gw];
    float s = di * di;
    float4 hv = h4[gw * 32 + lane];
    acc.x += s * hv.x; acc.y += s * hv.y; acc.z += s * hv.z; acc.w += s * hv.w;

    int e = g_rowptr[gw], ee = g_rowptr[gw + 1];
    for (; e + 4 <= ee; e += 4) {
        int c0 = g_col[e], c1 = g_col[e + 1], c2 = g_col[e + 2], c3 = g_col[e + 3];
        float w0 = g_wgt[e], w1 = g_wgt[e + 1], w2 = g_wgt[e + 2], w3 = g_wgt[e + 3];
        float4 v0 = h4[c0 * 32 + lane];
        float4 v1 = h4[c1 * 32 + lane];
        float4 v2 = h4[c2 * 32 + lane];
        float4 v3 = h4[c3 * 32 + lane];
        acc.x += w0 * v0.x; acc.y += w0 * v0.y; acc.z += w0 * v0.z; acc.w += w0 * v0.w;
        acc.x += w1 * v1.x; acc.y += w1 * v1.y; acc.z += w1 * v1.z; acc.w += w1 * v1.w;
        acc.x += w2 * v2.x; acc.y += w2 * v2.y; acc.z += w2 * v2.z; acc.w += w2 * v2.w;
        acc.x += w3 * v3.x; acc.y += w3 * v3.y; acc.z += w3 * v3.z; acc.w += w3 * v3.w;
    }
    for (; e < ee; e++) {
        int c = g_col[e];
        float w = g_wgt[e];
        float4 v = h4[c * 32 + lane];
        acc.x += w * v.x; acc.y += w * v.y; acc.z += w * v.z; acc.w += w * v.w;
    }
    if (relu) {
        acc.x = fmaxf(acc.x, 0.f); acc.y = fmaxf(acc.y, 0.f);
        acc.z = fmaxf(acc.z, 0.f); acc.w = fmaxf(acc.w, 0.f);
    }
    ((float4*)g_a)[gw * 32 + lane] = acc;
}

// ---------------- pool ----------------
__global__ void pool_kernel(float* __restrict__ out) {
    int g = blockIdx.x;
    int c = threadIdx.x;
    int sidx = g_gstart[g], eidx = g_gstart[g + 1];
    float acc = 0.f;
    int i = sidx;
    for (; i + 4 <= eidx; i += 4) {
        float t0 = g_a[i * 128 + c];
        float t1 = g_a[(i + 1) * 128 + c];
        float t2 = g_a[(i + 2) * 128 + c];
        float t3 = g_a[(i + 3) * 128 + c];
        acc += (t0 + t1) + (t2 + t3);
    }
    for (; i < eidx; i++) acc += g_a[i * 128 + c];
    out[g * 128 + c] = acc;
}

extern "C" void kernel_launch(void* const* d_in, const int* in_sizes, int n_in,
                              void* d_out, int out_size) {
    const float* x     = (const float*)d_in[0];
    const int*   ei    = (const int*)d_in[1];
    const int*   batch = (const int*)d_in[2];
    const float* W1    = (const float*)d_in[3];
    const float* b1    = (const float*)d_in[4];
    const float* W2    = (const float*)d_in[5];
    const float* b2    = (const float*)d_in[6];
    float* out = (float*)d_out;

    cudaFuncSetAttribute(gemm_mma_kernel, cudaFuncAttributeMaxDynamicSharedMemorySize, 65536);

    // graph prep
    init_kernel<<<(NN + 255) / 256, 256>>>();
    count_kernel<<<(NE + 255) / 256, 256>>>(ei);
    pack_kernel<<<32, 256>>>(W1, W2);
    blockscan_kernel<<<NSCANB, 256>>>();
    scansums_kernel<<<1, 256>>>();
    addoff_kernel<<<NSCANB, 256>>>(batch);
    fill_kernel<<<(NE + 255) / 256, 256>>>(ei);
    gfix_kernel<<<1, 32>>>();

    // layer 1
    gemm_mma_kernel<<<(NN + 127) / 128, 256, 65536>>>(x, 0, 0);
    agg_kernel<<<(NN * 32 + 255) / 256, 256>>>(b1, 1);
    // layer 2
    gemm_mma_kernel<<<(NN + 127) / 128, 256, 65536>>>(nullptr, 1, 1);
    agg_kernel<<<(NN * 32 + 255) / 256, 256>>>(b2, 0);
    // pool
    pool_kernel<<<NG, 128>>>(out);
}